// round 7
// baseline (speedup 1.0000x reference)
#include <cuda_runtime.h>
#include <cstdint>
#include <cstddef>

// ---------------- problem constants ----------------
#define HID   3072
#define HEADS 24
#define HD    128
#define SEQL  2048
#define MLP   12288
#define H1    (3*HID + MLP)   // 21504 = lin1 out
#define C2K   (HID + MLP)     // 15360 = lin2 in

// ---------------- device scratch (static, no allocations) ----------------
__device__ float g_svec[HID];                          // silu(vec)
__device__ float g_mod [3*HID];                        // shift | scale | gate
__device__ float g_xmod[(size_t)SEQL*HID];             // modulated LN(x)
__device__ float g_h   [(size_t)SEQL*H1];              // lin1 output
__device__ float g_q   [(size_t)HEADS*SEQL*HD];        // q (rope'd, pre-scaled)
__device__ float g_k   [(size_t)HEADS*SEQL*HD];        // k (rope'd)
__device__ float g_vt  [(size_t)HEADS*HD*SEQL];        // v transposed [h][d][l]
__device__ float g_s   [(size_t)HEADS*SEQL*SEQL];      // scores / probs
__device__ float g_c   [(size_t)SEQL*C2K];             // concat(attn, gelu(mlp))

// ---------------- helpers ----------------
__device__ __forceinline__ float to_tf32(float x) {
    uint32_t u;
    asm("cvt.rna.tf32.f32 %0, %1;" : "=r"(u) : "f"(x));
    return __uint_as_float(u);
}

__device__ __forceinline__ void mma8(float* d, const uint32_t* a, const uint32_t* b) {
    asm volatile(
        "mma.sync.aligned.m16n8k8.row.col.f32.tf32.tf32.f32 "
        "{%0,%1,%2,%3}, {%4,%5,%6,%7}, {%8,%9}, {%0,%1,%2,%3};\n"
        : "+f"(d[0]), "+f"(d[1]), "+f"(d[2]), "+f"(d[3])
        : "r"(a[0]), "r"(a[1]), "r"(a[2]), "r"(a[3]), "r"(b[0]), "r"(b[1]));
}

__device__ __forceinline__ float gelu1(float x) {
    float x3 = x * x * x;
    return 0.5f * x * (1.f + tanhf(0.7978845608028654f * (x + 0.044715f * x3)));
}

// ================= GEMM: C[b,m,n] = sum_k A[b,m,k]*B[b,n,k] (+bias)(*gate)(+resid) ===========
// TF32 tensor-core NT GEMM. All dims must be exact multiples of tiles (they are).
#define BM 128
#define BN 128
#define BKT 16
#define SPAD 8

__global__ __launch_bounds__(256)
void gemm_nt(const float* __restrict__ A, const float* __restrict__ B,
             const float* __restrict__ bias, const float* __restrict__ resid,
             const float* __restrict__ gate, float* __restrict__ C,
             int K, int lda, int ldb, int ldc,
             long long sA, long long sB, long long sC)
{
    __shared__ float As[2][BKT][BM + SPAD];
    __shared__ float Bs[2][BKT][BN + SPAD];

    const int tid  = threadIdx.x;
    const int lane = tid & 31;
    const int gid  = lane >> 2;
    const int tg   = lane & 3;
    const int warp = tid >> 5;
    const int wm   = (warp >> 2) * 64;   // 0 or 64
    const int wn   = (warp & 3) * 32;    // 0..96

    const int bm0 = blockIdx.y * BM;
    const int bn0 = blockIdx.x * BN;

    const float* Ab = A + (size_t)blockIdx.z * sA + (size_t)bm0 * lda;
    const float* Bb = B + (size_t)blockIdx.z * sB + (size_t)bn0 * ldb;

    const int fr = tid >> 2;         // row 0..63 (also +64)
    const int fk = (tid & 3) * 4;    // k-subvector

    float acc[4][4][4];
    #pragma unroll
    for (int i = 0; i < 4; ++i)
        #pragma unroll
        for (int j = 0; j < 4; ++j)
            #pragma unroll
            for (int v = 0; v < 4; ++v) acc[i][j][v] = 0.f;

    // prologue: tile 0 -> stage 0
    {
        float4 a0 = *(const float4*)(Ab + (size_t)fr * lda + fk);
        float4 a1 = *(const float4*)(Ab + (size_t)(fr + 64) * lda + fk);
        float4 b0 = *(const float4*)(Bb + (size_t)fr * ldb + fk);
        float4 b1 = *(const float4*)(Bb + (size_t)(fr + 64) * ldb + fk);
        As[0][fk+0][fr]    = to_tf32(a0.x); As[0][fk+1][fr]    = to_tf32(a0.y);
        As[0][fk+2][fr]    = to_tf32(a0.z); As[0][fk+3][fr]    = to_tf32(a0.w);
        As[0][fk+0][fr+64] = to_tf32(a1.x); As[0][fk+1][fr+64] = to_tf32(a1.y);
        As[0][fk+2][fr+64] = to_tf32(a1.z); As[0][fk+3][fr+64] = to_tf32(a1.w);
        Bs[0][fk+0][fr]    = to_tf32(b0.x); Bs[0][fk+1][fr]    = to_tf32(b0.y);
        Bs[0][fk+2][fr]    = to_tf32(b0.z); Bs[0][fk+3][fr]    = to_tf32(b0.w);
        Bs[0][fk+0][fr+64] = to_tf32(b1.x); Bs[0][fk+1][fr+64] = to_tf32(b1.y);
        Bs[0][fk+2][fr+64] = to_tf32(b1.z); Bs[0][fk+3][fr+64] = to_tf32(b1.w);
    }
    __syncthreads();

    const int nk = K / BKT;
    int s = 0;
    for (int kt = 0; kt < nk; ++kt) {
        float4 na0, na1, nb0, nb1;
        const bool hn = (kt + 1) < nk;
        if (hn) {
            const int k0 = (kt + 1) * BKT;
            na0 = *(const float4*)(Ab + (size_t)fr * lda + k0 + fk);
            na1 = *(const float4*)(Ab + (size_t)(fr + 64) * lda + k0 + fk);
            nb0 = *(const float4*)(Bb + (size_t)fr * ldb + k0 + fk);
            nb1 = *(const float4*)(Bb + (size_t)(fr + 64) * ldb + k0 + fk);
        }
        #pragma unroll
        for (int kk = 0; kk < BKT; kk += 8) {
            uint32_t af[4][4], bf[4][2];
            #pragma unroll
            for (int im = 0; im < 4; ++im) {
                const int m = wm + im * 16 + gid;
                af[im][0] = __float_as_uint(As[s][kk + tg    ][m]);
                af[im][1] = __float_as_uint(As[s][kk + tg    ][m + 8]);
                af[im][2] = __float_as_uint(As[s][kk + tg + 4][m]);
                af[im][3] = __float_as_uint(As[s][kk + tg + 4][m + 8]);
            }
            #pragma unroll
            for (int in = 0; in < 4; ++in) {
                const int n = wn + in * 8 + gid;
                bf[in][0] = __float_as_uint(Bs[s][kk + tg    ][n]);
                bf[in][1] = __float_as_uint(Bs[s][kk + tg + 4][n]);
            }
            #pragma unroll
            for (int im = 0; im < 4; ++im)
                #pragma unroll
                for (int in = 0; in < 4; ++in)
                    mma8(acc[im][in], af[im], bf[in]);
        }
        if (hn) {
            const int t = s ^ 1;
            As[t][fk+0][fr]    = to_tf32(na0.x); As[t][fk+1][fr]    = to_tf32(na0.y);
            As[t][fk+2][fr]    = to_tf32(na0.z); As[t][fk+3][fr]    = to_tf32(na0.w);
            As[t][fk+0][fr+64] = to_tf32(na1.x); As[t][fk+1][fr+64] = to_tf32(na1.y);
            As[t][fk+2][fr+64] = to_tf32(na1.z); As[t][fk+3][fr+64] = to_tf32(na1.w);
            Bs[t][fk+0][fr]    = to_tf32(nb0.x); Bs[t][fk+1][fr]    = to_tf32(nb0.y);
            Bs[t][fk+2][fr]    = to_tf32(nb0.z); Bs[t][fk+3][fr]    = to_tf32(nb0.w);
            Bs[t][fk+0][fr+64] = to_tf32(nb1.x); Bs[t][fk+1][fr+64] = to_tf32(nb1.y);
            Bs[t][fk+2][fr+64] = to_tf32(nb1.z); Bs[t][fk+3][fr+64] = to_tf32(nb1.w);
            __syncthreads();
            s = t;
        }
    }

    // epilogue
    float* Cb = C + (size_t)blockIdx.z * sC;
    #pragma unroll
    for (int im = 0; im < 4; ++im) {
        #pragma unroll
        for (int in = 0; in < 4; ++in) {
            const int r  = bm0 + wm + im * 16 + gid;
            const int cc = bn0 + wn + in * 8 + 2 * tg;
            #pragma unroll
            for (int v = 0; v < 4; ++v) {
                const int rr = r + (v >> 1) * 8;
                const int c2 = cc + (v & 1);
                float val = acc[im][in][v];
                if (bias)  val += __ldg(bias + c2);
                if (gate)  val *= __ldg(gate + c2);
                if (resid) val += __ldg(resid + (size_t)rr * ldc + c2);
                Cb[(size_t)rr * ldc + c2] = val;
            }
        }
    }
}

// ================= small kernels =================

__global__ void silu_k(const float* __restrict__ v) {
    int i = blockIdx.x * blockDim.x + threadIdx.x;
    float x = v[i];
    g_svec[i] = x / (1.f + __expf(-x));
}

// m[i] = dot(silu(vec), mod_w[i,:]) + mod_b[i]   (one warp per output row)
__global__ __launch_bounds__(256)
void mod_gemv(const float* __restrict__ W, const float* __restrict__ b) {
    const int warp = threadIdx.x >> 5, lane = threadIdx.x & 31;
    const int row  = blockIdx.x * 8 + warp;
    const float* w = W + (size_t)row * HID;
    float s = 0.f;
    for (int j = lane * 4; j < HID; j += 128) {
        float4 wv = *(const float4*)(w + j);
        float4 vv = *(const float4*)(g_svec + j);
        s += wv.x * vv.x + wv.y * vv.y + wv.z * vv.z + wv.w * vv.w;
    }
    #pragma unroll
    for (int o = 16; o; o >>= 1) s += __shfl_down_sync(0xffffffffu, s, o);
    if (!lane) g_mod[row] = s + b[row];
}

// x_mod = (1+scale)*LN(x) + shift, one block per row
__global__ __launch_bounds__(256)
void ln_mod(const float* __restrict__ x) {
    const int l = blockIdx.x, tid = threadIdx.x;
    const float* xr = x + (size_t)l * HID;
    float4 v[3];
    float sum = 0.f, ss = 0.f;
    #pragma unroll
    for (int i = 0; i < 3; ++i) {
        v[i] = *(const float4*)(xr + (tid + i * 256) * 4);
        sum += v[i].x + v[i].y + v[i].z + v[i].w;
        ss  += v[i].x * v[i].x + v[i].y * v[i].y + v[i].z * v[i].z + v[i].w * v[i].w;
    }
    __shared__ float rs[2][8];
    #pragma unroll
    for (int o = 16; o; o >>= 1) {
        sum += __shfl_down_sync(0xffffffffu, sum, o);
        ss  += __shfl_down_sync(0xffffffffu, ss,  o);
    }
    if (!(tid & 31)) { rs[0][tid >> 5] = sum; rs[1][tid >> 5] = ss; }
    __syncthreads();
    sum = 0.f; ss = 0.f;
    #pragma unroll
    for (int i = 0; i < 8; ++i) { sum += rs[0][i]; ss += rs[1][i]; }
    const float mu   = sum * (1.f / HID);
    const float var  = ss * (1.f / HID) - mu * mu;
    const float rstd = rsqrtf(var + 1e-6f);
    #pragma unroll
    for (int i = 0; i < 3; ++i) {
        const int c = (tid + i * 256) * 4;
        float4 sh = *(const float4*)(g_mod + c);
        float4 sc = *(const float4*)(g_mod + HID + c);
        float4 o;
        o.x = (1.f + sc.x) * ((v[i].x - mu) * rstd) + sh.x;
        o.y = (1.f + sc.y) * ((v[i].y - mu) * rstd) + sh.y;
        o.z = (1.f + sc.z) * ((v[i].z - mu) * rstd) + sh.z;
        o.w = (1.f + sc.w) * ((v[i].w - mu) * rstd) + sh.w;
        *(float4*)(g_xmod + (size_t)l * HID + c) = o;
    }
}

// rmsnorm(q,k) + rope + scatter q/k/vT. One block (64 threads) per (head, l); thread j owns pair (2j,2j+1)
__global__ void qkv_prep(const float* __restrict__ pe,
                         const float* __restrict__ qs, const float* __restrict__ ks) {
    const int head = blockIdx.x, l = blockIdx.y, j = threadIdx.x;
    const float* hr = g_h + (size_t)l * H1 + head * HD;
    float q0 = hr[2*j],        q1 = hr[2*j + 1];
    float k0 = hr[HID + 2*j],  k1 = hr[HID + 2*j + 1];
    float v0 = hr[2*HID + 2*j], v1 = hr[2*HID + 2*j + 1];

    float sq = q0*q0 + q1*q1, sk = k0*k0 + k1*k1;
    #pragma unroll
    for (int o = 16; o; o >>= 1) {
        sq += __shfl_down_sync(0xffffffffu, sq, o);
        sk += __shfl_down_sync(0xffffffffu, sk, o);
    }
    __shared__ float red[2][2];
    const int w = j >> 5, lane = j & 31;
    if (!lane) { red[0][w] = sq; red[1][w] = sk; }
    __syncthreads();
    const float rq = rsqrtf((red[0][0] + red[0][1]) * (1.f / HD) + 1e-6f);
    const float rk = rsqrtf((red[1][0] + red[1][1]) * (1.f / HD) + 1e-6f);

    q0 = q0 * rq * qs[2*j]; q1 = q1 * rq * qs[2*j + 1];
    k0 = k0 * rk * ks[2*j]; k1 = k1 * rk * ks[2*j + 1];

    const float* p = pe + ((size_t)l * (HD/2) + j) * 4;   // [j][i0][i1]
    const float p00 = p[0], p01 = p[1], p10 = p[2], p11 = p[3];
    const float qo0 = p00 * q0 + p01 * q1, qo1 = p10 * q0 + p11 * q1;
    const float ko0 = p00 * k0 + p01 * k1, ko1 = p10 * k0 + p11 * k1;

    const float sm = 0.08838834764831845f;  // 1/sqrt(128)
    const size_t qoff = ((size_t)head * SEQL + l) * HD + 2*j;
    g_q[qoff]     = qo0 * sm;  g_q[qoff + 1] = qo1 * sm;
    g_k[qoff]     = ko0;       g_k[qoff + 1] = ko1;
    const size_t voff = ((size_t)head * HD + 2*j) * SEQL + l;
    g_vt[voff]        = v0;
    g_vt[voff + SEQL] = v1;
}

// gelu(mlp half of h) -> concat buffer columns [HID:)
__global__ void gelu_k() {
    const int idx = blockIdx.x * blockDim.x + threadIdx.x;  // float4 id
    const int row = idx / (MLP / 4);
    const int col = (idx % (MLP / 4)) * 4;
    float4 v = *(const float4*)(g_h + (size_t)row * H1 + 3*HID + col);
    v.x = gelu1(v.x); v.y = gelu1(v.y); v.z = gelu1(v.z); v.w = gelu1(v.w);
    *(float4*)(g_c + (size_t)row * C2K + HID + col) = v;
}

// row softmax over 2048, in place on g_s. One block per row.
__global__ __launch_bounds__(256)
void softmax_k() {
    float* p = g_s + (size_t)blockIdx.x * SEQL;
    const int tid = threadIdx.x;
    float4 v0 = *(const float4*)(p + tid * 4);
    float4 v1 = *(const float4*)(p + 1024 + tid * 4);
    float mx = fmaxf(fmaxf(fmaxf(v0.x, v0.y), fmaxf(v0.z, v0.w)),
                     fmaxf(fmaxf(v1.x, v1.y), fmaxf(v1.z, v1.w)));
    __shared__ float rs[8];
    #pragma unroll
    for (int o = 16; o; o >>= 1) mx = fmaxf(mx, __shfl_xor_sync(0xffffffffu, mx, o));
    if (!(tid & 31)) rs[tid >> 5] = mx;
    __syncthreads();
    float gmx = rs[0];
    #pragma unroll
    for (int i = 1; i < 8; ++i) gmx = fmaxf(gmx, rs[i]);
    __syncthreads();
    float sm = 0.f;
    v0.x = __expf(v0.x - gmx); sm += v0.x;  v0.y = __expf(v0.y - gmx); sm += v0.y;
    v0.z = __expf(v0.z - gmx); sm += v0.z;  v0.w = __expf(v0.w - gmx); sm += v0.w;
    v1.x = __expf(v1.x - gmx); sm += v1.x;  v1.y = __expf(v1.y - gmx); sm += v1.y;
    v1.z = __expf(v1.z - gmx); sm += v1.z;  v1.w = __expf(v1.w - gmx); sm += v1.w;
    #pragma unroll
    for (int o = 16; o; o >>= 1) sm += __shfl_xor_sync(0xffffffffu, sm, o);
    if (!(tid & 31)) rs[tid >> 5] = sm;
    __syncthreads();
    float gs = 0.f;
    #pragma unroll
    for (int i = 0; i < 8; ++i) gs += rs[i];
    const float inv = 1.f / gs;
    v0.x *= inv; v0.y *= inv; v0.z *= inv; v0.w *= inv;
    v1.x *= inv; v1.y *= inv; v1.z *= inv; v1.w *= inv;
    *(float4*)(p + tid * 4) = v0;
    *(float4*)(p + 1024 + tid * 4) = v1;
}

// ================= launcher =================
extern "C" void kernel_launch(void* const* d_in, const int* in_sizes, int n_in,
                              void* d_out, int out_size) {
    const float* x       = (const float*)d_in[0];
    const float* vec     = (const float*)d_in[1];
    const float* pe      = (const float*)d_in[2];
    const float* mod_w   = (const float*)d_in[3];
    const float* mod_b   = (const float*)d_in[4];
    const float* lin1_w  = (const float*)d_in[5];
    const float* lin1_b  = (const float*)d_in[6];
    const float* lin2_w  = (const float*)d_in[7];
    const float* lin2_b  = (const float*)d_in[8];
    const float* q_scale = (const float*)d_in[9];
    const float* k_scale = (const float*)d_in[10];
    float* out = (float*)d_out;

    float *p_xmod, *p_h, *p_q, *p_k, *p_vt, *p_s, *p_c, *p_mod;
    cudaGetSymbolAddress((void**)&p_xmod, g_xmod);
    cudaGetSymbolAddress((void**)&p_h,    g_h);
    cudaGetSymbolAddress((void**)&p_q,    g_q);
    cudaGetSymbolAddress((void**)&p_k,    g_k);
    cudaGetSymbolAddress((void**)&p_vt,   g_vt);
    cudaGetSymbolAddress((void**)&p_s,    g_s);
    cudaGetSymbolAddress((void**)&p_c,    g_c);
    cudaGetSymbolAddress((void**)&p_mod,  g_mod);

    // 1) modulation vector
    silu_k<<<HID / 256, 256>>>(vec);
    mod_gemv<<<(3 * HID) / 8, 256>>>(mod_w, mod_b);

    // 2) layernorm + modulation
    ln_mod<<<SEQL, 256>>>(x);

    // 3) lin1: h = x_mod @ lin1_w^T + b   [2048 x 21504]
    gemm_nt<<<dim3(H1 / BN, SEQL / BM, 1), 256>>>(
        p_xmod, lin1_w, lin1_b, nullptr, nullptr, p_h,
        HID, HID, HID, H1, 0, 0, 0);

    // 4) qkv prep (rmsnorm + rope + transpose V) and gelu(mlp)
    qkv_prep<<<dim3(HEADS, SEQL), 64>>>(pe, q_scale, k_scale);
    gelu_k<<<(SEQL * (MLP / 4)) / 256, 256>>>();

    // 5) scores = q @ k^T (batched over heads), softmax-scale folded into q
    gemm_nt<<<dim3(SEQL / BN, SEQL / BM, HEADS), 256>>>(
        p_q, p_k, nullptr, nullptr, nullptr, p_s,
        HD, HD, HD, SEQL,
        (long long)SEQL * HD, (long long)SEQL * HD, (long long)SEQL * SEQL);

    // 6) softmax rows
    softmax_k<<<HEADS * SEQL, 256>>>();

    // 7) attn = P @ V  -> concat buffer columns [0:HID), interleaved by head
    gemm_nt<<<dim3(HD / BN, SEQL / BM, HEADS), 256>>>(
        p_s, p_vt, nullptr, nullptr, nullptr, p_c,
        SEQL, SEQL, SEQL, C2K,
        (long long)SEQL * SEQL, (long long)HD * SEQL, (long long)HD);

    // 8) lin2 + gate + residual fused: out = x + gate * (c @ lin2_w^T + b)
    gemm_nt<<<dim3(HID / BN, SEQL / BM, 1), 256>>>(
        p_c, lin2_w, lin2_b, x, p_mod + 2 * HID, out,
        C2K, C2K, C2K, HID, 0, 0, 0);
}

// round 8
// speedup vs baseline: 1.0030x; 1.0030x over previous
#include <cuda_runtime.h>
#include <cstdint>
#include <cstddef>

// ---------------- problem constants ----------------
#define HID   3072
#define HEADS 24
#define HD    128
#define SEQL  2048
#define MLP   12288
#define H1    (3*HID + MLP)   // 21504 = lin1 out
#define C2K   (HID + MLP)     // 15360 = lin2 in

// ---------------- device scratch (static, no allocations) ----------------
__device__ float g_svec[HID];                          // silu(vec)
__device__ float g_mod [3*HID];                        // shift | scale | gate
__device__ float g_xmod[(size_t)SEQL*HID];             // modulated LN(x)
__device__ float g_h   [(size_t)SEQL*H1];              // lin1 output
__device__ float g_q   [(size_t)HEADS*SEQL*HD];        // q (rope'd, pre-scaled)
__device__ float g_k   [(size_t)HEADS*SEQL*HD];        // k (rope'd)
__device__ float g_vt  [(size_t)HEADS*HD*SEQL];        // v transposed [h][d][l]
__device__ float g_s   [(size_t)HEADS*SEQL*SEQL];      // scores / probs
__device__ float g_c   [(size_t)SEQL*C2K];             // concat(attn, gelu(mlp))

// ---------------- helpers ----------------
__device__ __forceinline__ float to_tf32(float x) {
    uint32_t u;
    asm("cvt.rna.tf32.f32 %0, %1;" : "=r"(u) : "f"(x));
    return __uint_as_float(u);
}

__device__ __forceinline__ void mma8(float* d, const uint32_t* a, const uint32_t* b) {
    asm volatile(
        "mma.sync.aligned.m16n8k8.row.col.f32.tf32.tf32.f32 "
        "{%0,%1,%2,%3}, {%4,%5,%6,%7}, {%8,%9}, {%0,%1,%2,%3};\n"
        : "+f"(d[0]), "+f"(d[1]), "+f"(d[2]), "+f"(d[3])
        : "r"(a[0]), "r"(a[1]), "r"(a[2]), "r"(a[3]), "r"(b[0]), "r"(b[1]));
}

__device__ __forceinline__ float gelu1(float x) {
    float x3 = x * x * x;
    return 0.5f * x * (1.f + tanhf(0.7978845608028654f * (x + 0.044715f * x3)));
}

// ================= GEMM: C[b,m,n] = sum_k A[b,m,k]*B[b,n,k] (+bias)(*gate)(+resid) ===========
// TF32 tensor-core NT GEMM. All dims must be exact multiples of tiles (they are).
#define BM 128
#define BN 128
#define BKT 16
#define SPAD 8

__global__ __launch_bounds__(256)
void gemm_nt(const float* __restrict__ A, const float* __restrict__ B,
             const float* __restrict__ bias, const float* __restrict__ resid,
             const float* __restrict__ gate, float* __restrict__ C,
             int K, int lda, int ldb, int ldc,
             long long sA, long long sB, long long sC)
{
    __shared__ float As[2][BKT][BM + SPAD];
    __shared__ float Bs[2][BKT][BN + SPAD];

    const int tid  = threadIdx.x;
    const int lane = tid & 31;
    const int gid  = lane >> 2;
    const int tg   = lane & 3;
    const int warp = tid >> 5;
    const int wm   = (warp >> 2) * 64;   // 0 or 64
    const int wn   = (warp & 3) * 32;    // 0..96

    const int bm0 = blockIdx.y * BM;
    const int bn0 = blockIdx.x * BN;

    const float* Ab = A + (size_t)blockIdx.z * sA + (size_t)bm0 * lda;
    const float* Bb = B + (size_t)blockIdx.z * sB + (size_t)bn0 * ldb;

    const int fr = tid >> 2;         // row 0..63 (also +64)
    const int fk = (tid & 3) * 4;    // k-subvector

    float acc[4][4][4];
    #pragma unroll
    for (int i = 0; i < 4; ++i)
        #pragma unroll
        for (int j = 0; j < 4; ++j)
            #pragma unroll
            for (int v = 0; v < 4; ++v) acc[i][j][v] = 0.f;

    // prologue: tile 0 -> stage 0
    {
        float4 a0 = *(const float4*)(Ab + (size_t)fr * lda + fk);
        float4 a1 = *(const float4*)(Ab + (size_t)(fr + 64) * lda + fk);
        float4 b0 = *(const float4*)(Bb + (size_t)fr * ldb + fk);
        float4 b1 = *(const float4*)(Bb + (size_t)(fr + 64) * ldb + fk);
        As[0][fk+0][fr]    = to_tf32(a0.x); As[0][fk+1][fr]    = to_tf32(a0.y);
        As[0][fk+2][fr]    = to_tf32(a0.z); As[0][fk+3][fr]    = to_tf32(a0.w);
        As[0][fk+0][fr+64] = to_tf32(a1.x); As[0][fk+1][fr+64] = to_tf32(a1.y);
        As[0][fk+2][fr+64] = to_tf32(a1.z); As[0][fk+3][fr+64] = to_tf32(a1.w);
        Bs[0][fk+0][fr]    = to_tf32(b0.x); Bs[0][fk+1][fr]    = to_tf32(b0.y);
        Bs[0][fk+2][fr]    = to_tf32(b0.z); Bs[0][fk+3][fr]    = to_tf32(b0.w);
        Bs[0][fk+0][fr+64] = to_tf32(b1.x); Bs[0][fk+1][fr+64] = to_tf32(b1.y);
        Bs[0][fk+2][fr+64] = to_tf32(b1.z); Bs[0][fk+3][fr+64] = to_tf32(b1.w);
    }
    __syncthreads();

    const int nk = K / BKT;
    int s = 0;
    for (int kt = 0; kt < nk; ++kt) {
        float4 na0, na1, nb0, nb1;
        const bool hn = (kt + 1) < nk;
        if (hn) {
            const int k0 = (kt + 1) * BKT;
            na0 = *(const float4*)(Ab + (size_t)fr * lda + k0 + fk);
            na1 = *(const float4*)(Ab + (size_t)(fr + 64) * lda + k0 + fk);
            nb0 = *(const float4*)(Bb + (size_t)fr * ldb + k0 + fk);
            nb1 = *(const float4*)(Bb + (size_t)(fr + 64) * ldb + k0 + fk);
        }
        #pragma unroll
        for (int kk = 0; kk < BKT; kk += 8) {
            uint32_t af[4][4], bf[4][2];
            #pragma unroll
            for (int im = 0; im < 4; ++im) {
                const int m = wm + im * 16 + gid;
                af[im][0] = __float_as_uint(As[s][kk + tg    ][m]);
                af[im][1] = __float_as_uint(As[s][kk + tg    ][m + 8]);
                af[im][2] = __float_as_uint(As[s][kk + tg + 4][m]);
                af[im][3] = __float_as_uint(As[s][kk + tg + 4][m + 8]);
            }
            #pragma unroll
            for (int in = 0; in < 4; ++in) {
                const int n = wn + in * 8 + gid;
                bf[in][0] = __float_as_uint(Bs[s][kk + tg    ][n]);
                bf[in][1] = __float_as_uint(Bs[s][kk + tg + 4][n]);
            }
            #pragma unroll
            for (int im = 0; im < 4; ++im)
                #pragma unroll
                for (int in = 0; in < 4; ++in)
                    mma8(acc[im][in], af[im], bf[in]);
        }
        if (hn) {
            const int t = s ^ 1;
            As[t][fk+0][fr]    = to_tf32(na0.x); As[t][fk+1][fr]    = to_tf32(na0.y);
            As[t][fk+2][fr]    = to_tf32(na0.z); As[t][fk+3][fr]    = to_tf32(na0.w);
            As[t][fk+0][fr+64] = to_tf32(na1.x); As[t][fk+1][fr+64] = to_tf32(na1.y);
            As[t][fk+2][fr+64] = to_tf32(na1.z); As[t][fk+3][fr+64] = to_tf32(na1.w);
            Bs[t][fk+0][fr]    = to_tf32(nb0.x); Bs[t][fk+1][fr]    = to_tf32(nb0.y);
            Bs[t][fk+2][fr]    = to_tf32(nb0.z); Bs[t][fk+3][fr]    = to_tf32(nb0.w);
            Bs[t][fk+0][fr+64] = to_tf32(nb1.x); Bs[t][fk+1][fr+64] = to_tf32(nb1.y);
            Bs[t][fk+2][fr+64] = to_tf32(nb1.z); Bs[t][fk+3][fr+64] = to_tf32(nb1.w);
            __syncthreads();
            s = t;
        }
    }

    // epilogue
    float* Cb = C + (size_t)blockIdx.z * sC;
    #pragma unroll
    for (int im = 0; im < 4; ++im) {
        #pragma unroll
        for (int in = 0; in < 4; ++in) {
            const int r  = bm0 + wm + im * 16 + gid;
            const int cc = bn0 + wn + in * 8 + 2 * tg;
            #pragma unroll
            for (int v = 0; v < 4; ++v) {
                const int rr = r + (v >> 1) * 8;
                const int c2 = cc + (v & 1);
                float val = acc[im][in][v];
                if (bias)  val += __ldg(bias + c2);
                if (gate)  val *= __ldg(gate + c2);
                if (resid) val += __ldg(resid + (size_t)rr * ldc + c2);
                Cb[(size_t)rr * ldc + c2] = val;
            }
        }
    }
}

// ================= small kernels =================

__global__ void silu_k(const float* __restrict__ v) {
    int i = blockIdx.x * blockDim.x + threadIdx.x;
    float x = v[i];
    g_svec[i] = x / (1.f + __expf(-x));
}

// m[i] = dot(silu(vec), mod_w[i,:]) + mod_b[i]   (one warp per output row)
__global__ __launch_bounds__(256)
void mod_gemv(const float* __restrict__ W, const float* __restrict__ b) {
    const int warp = threadIdx.x >> 5, lane = threadIdx.x & 31;
    const int row  = blockIdx.x * 8 + warp;
    const float* w = W + (size_t)row * HID;
    float s = 0.f;
    for (int j = lane * 4; j < HID; j += 128) {
        float4 wv = *(const float4*)(w + j);
        float4 vv = *(const float4*)(g_svec + j);
        s += wv.x * vv.x + wv.y * vv.y + wv.z * vv.z + wv.w * vv.w;
    }
    #pragma unroll
    for (int o = 16; o; o >>= 1) s += __shfl_down_sync(0xffffffffu, s, o);
    if (!lane) g_mod[row] = s + b[row];
}

// x_mod = (1+scale)*LN(x) + shift, one block per row
__global__ __launch_bounds__(256)
void ln_mod(const float* __restrict__ x) {
    const int l = blockIdx.x, tid = threadIdx.x;
    const float* xr = x + (size_t)l * HID;
    float4 v[3];
    float sum = 0.f, ss = 0.f;
    #pragma unroll
    for (int i = 0; i < 3; ++i) {
        v[i] = *(const float4*)(xr + (tid + i * 256) * 4);
        sum += v[i].x + v[i].y + v[i].z + v[i].w;
        ss  += v[i].x * v[i].x + v[i].y * v[i].y + v[i].z * v[i].z + v[i].w * v[i].w;
    }
    __shared__ float rs[2][8];
    #pragma unroll
    for (int o = 16; o; o >>= 1) {
        sum += __shfl_down_sync(0xffffffffu, sum, o);
        ss  += __shfl_down_sync(0xffffffffu, ss,  o);
    }
    if (!(tid & 31)) { rs[0][tid >> 5] = sum; rs[1][tid >> 5] = ss; }
    __syncthreads();
    sum = 0.f; ss = 0.f;
    #pragma unroll
    for (int i = 0; i < 8; ++i) { sum += rs[0][i]; ss += rs[1][i]; }
    const float mu   = sum * (1.f / HID);
    const float var  = ss * (1.f / HID) - mu * mu;
    const float rstd = rsqrtf(var + 1e-6f);
    #pragma unroll
    for (int i = 0; i < 3; ++i) {
        const int c = (tid + i * 256) * 4;
        float4 sh = *(const float4*)(g_mod + c);
        float4 sc = *(const float4*)(g_mod + HID + c);
        float4 o;
        o.x = (1.f + sc.x) * ((v[i].x - mu) * rstd) + sh.x;
        o.y = (1.f + sc.y) * ((v[i].y - mu) * rstd) + sh.y;
        o.z = (1.f + sc.z) * ((v[i].z - mu) * rstd) + sh.z;
        o.w = (1.f + sc.w) * ((v[i].w - mu) * rstd) + sh.w;
        *(float4*)(g_xmod + (size_t)l * HID + c) = o;
    }
}

// rmsnorm(q,k) + rope + scatter q/k/vT. One block (64 threads) per (head, l); thread j owns pair (2j,2j+1)
__global__ void qkv_prep(const float* __restrict__ pe,
                         const float* __restrict__ qs, const float* __restrict__ ks) {
    const int head = blockIdx.x, l = blockIdx.y, j = threadIdx.x;
    const float* hr = g_h + (size_t)l * H1 + head * HD;
    float q0 = hr[2*j],        q1 = hr[2*j + 1];
    float k0 = hr[HID + 2*j],  k1 = hr[HID + 2*j + 1];
    float v0 = hr[2*HID + 2*j], v1 = hr[2*HID + 2*j + 1];

    float sq = q0*q0 + q1*q1, sk = k0*k0 + k1*k1;
    #pragma unroll
    for (int o = 16; o; o >>= 1) {
        sq += __shfl_down_sync(0xffffffffu, sq, o);
        sk += __shfl_down_sync(0xffffffffu, sk, o);
    }
    __shared__ float red[2][2];
    const int w = j >> 5, lane = j & 31;
    if (!lane) { red[0][w] = sq; red[1][w] = sk; }
    __syncthreads();
    const float rq = rsqrtf((red[0][0] + red[0][1]) * (1.f / HD) + 1e-6f);
    const float rk = rsqrtf((red[1][0] + red[1][1]) * (1.f / HD) + 1e-6f);

    q0 = q0 * rq * qs[2*j]; q1 = q1 * rq * qs[2*j + 1];
    k0 = k0 * rk * ks[2*j]; k1 = k1 * rk * ks[2*j + 1];

    const float* p = pe + ((size_t)l * (HD/2) + j) * 4;   // [j][i0][i1]
    const float p00 = p[0], p01 = p[1], p10 = p[2], p11 = p[3];
    const float qo0 = p00 * q0 + p01 * q1, qo1 = p10 * q0 + p11 * q1;
    const float ko0 = p00 * k0 + p01 * k1, ko1 = p10 * k0 + p11 * k1;

    const float sm = 0.08838834764831845f;  // 1/sqrt(128)
    const size_t qoff = ((size_t)head * SEQL + l) * HD + 2*j;
    g_q[qoff]     = qo0 * sm;  g_q[qoff + 1] = qo1 * sm;
    g_k[qoff]     = ko0;       g_k[qoff + 1] = ko1;
    const size_t voff = ((size_t)head * HD + 2*j) * SEQL + l;
    g_vt[voff]        = v0;
    g_vt[voff + SEQL] = v1;
}

// gelu(mlp half of h) -> concat buffer columns [HID:)
__global__ void gelu_k() {
    const int idx = blockIdx.x * blockDim.x + threadIdx.x;  // float4 id
    const int row = idx / (MLP / 4);
    const int col = (idx % (MLP / 4)) * 4;
    float4 v = *(const float4*)(g_h + (size_t)row * H1 + 3*HID + col);
    v.x = gelu1(v.x); v.y = gelu1(v.y); v.z = gelu1(v.z); v.w = gelu1(v.w);
    *(float4*)(g_c + (size_t)row * C2K + HID + col) = v;
}

// row softmax over 2048, in place on g_s. One block per row.
__global__ __launch_bounds__(256)
void softmax_k() {
    float* p = g_s + (size_t)blockIdx.x * SEQL;
    const int tid = threadIdx.x;
    float4 v0 = *(const float4*)(p + tid * 4);
    float4 v1 = *(const float4*)(p + 1024 + tid * 4);
    float mx = fmaxf(fmaxf(fmaxf(v0.x, v0.y), fmaxf(v0.z, v0.w)),
                     fmaxf(fmaxf(v1.x, v1.y), fmaxf(v1.z, v1.w)));
    __shared__ float rs[8];
    #pragma unroll
    for (int o = 16; o; o >>= 1) mx = fmaxf(mx, __shfl_xor_sync(0xffffffffu, mx, o));
    if (!(tid & 31)) rs[tid >> 5] = mx;
    __syncthreads();
    float gmx = rs[0];
    #pragma unroll
    for (int i = 1; i < 8; ++i) gmx = fmaxf(gmx, rs[i]);
    __syncthreads();
    float sm = 0.f;
    v0.x = __expf(v0.x - gmx); sm += v0.x;  v0.y = __expf(v0.y - gmx); sm += v0.y;
    v0.z = __expf(v0.z - gmx); sm += v0.z;  v0.w = __expf(v0.w - gmx); sm += v0.w;
    v1.x = __expf(v1.x - gmx); sm += v1.x;  v1.y = __expf(v1.y - gmx); sm += v1.y;
    v1.z = __expf(v1.z - gmx); sm += v1.z;  v1.w = __expf(v1.w - gmx); sm += v1.w;
    #pragma unroll
    for (int o = 16; o; o >>= 1) sm += __shfl_xor_sync(0xffffffffu, sm, o);
    if (!(tid & 31)) rs[tid >> 5] = sm;
    __syncthreads();
    float gs = 0.f;
    #pragma unroll
    for (int i = 0; i < 8; ++i) gs += rs[i];
    const float inv = 1.f / gs;
    v0.x *= inv; v0.y *= inv; v0.z *= inv; v0.w *= inv;
    v1.x *= inv; v1.y *= inv; v1.z *= inv; v1.w *= inv;
    *(float4*)(p + tid * 4) = v0;
    *(float4*)(p + 1024 + tid * 4) = v1;
}

// ================= launcher =================
extern "C" void kernel_launch(void* const* d_in, const int* in_sizes, int n_in,
                              void* d_out, int out_size) {
    const float* x       = (const float*)d_in[0];
    const float* vec     = (const float*)d_in[1];
    const float* pe      = (const float*)d_in[2];
    const float* mod_w   = (const float*)d_in[3];
    const float* mod_b   = (const float*)d_in[4];
    const float* lin1_w  = (const float*)d_in[5];
    const float* lin1_b  = (const float*)d_in[6];
    const float* lin2_w  = (const float*)d_in[7];
    const float* lin2_b  = (const float*)d_in[8];
    const float* q_scale = (const float*)d_in[9];
    const float* k_scale = (const float*)d_in[10];
    float* out = (float*)d_out;

    float *p_xmod, *p_h, *p_q, *p_k, *p_vt, *p_s, *p_c, *p_mod;
    cudaGetSymbolAddress((void**)&p_xmod, g_xmod);
    cudaGetSymbolAddress((void**)&p_h,    g_h);
    cudaGetSymbolAddress((void**)&p_q,    g_q);
    cudaGetSymbolAddress((void**)&p_k,    g_k);
    cudaGetSymbolAddress((void**)&p_vt,   g_vt);
    cudaGetSymbolAddress((void**)&p_s,    g_s);
    cudaGetSymbolAddress((void**)&p_c,    g_c);
    cudaGetSymbolAddress((void**)&p_mod,  g_mod);

    // 1) modulation vector
    silu_k<<<HID / 256, 256>>>(vec);
    mod_gemv<<<(3 * HID) / 8, 256>>>(mod_w, mod_b);

    // 2) layernorm + modulation
    ln_mod<<<SEQL, 256>>>(x);

    // 3) lin1: h = x_mod @ lin1_w^T + b   [2048 x 21504]
    gemm_nt<<<dim3(H1 / BN, SEQL / BM, 1), 256>>>(
        p_xmod, lin1_w, lin1_b, nullptr, nullptr, p_h,
        HID, HID, HID, H1, 0, 0, 0);

    // 4) qkv prep (rmsnorm + rope + transpose V) and gelu(mlp)
    qkv_prep<<<dim3(HEADS, SEQL), 64>>>(pe, q_scale, k_scale);
    gelu_k<<<(SEQL * (MLP / 4)) / 256, 256>>>();

    // 5) scores = q @ k^T (batched over heads), softmax-scale folded into q
    gemm_nt<<<dim3(SEQL / BN, SEQL / BM, HEADS), 256>>>(
        p_q, p_k, nullptr, nullptr, nullptr, p_s,
        HD, HD, HD, SEQL,
        (long long)SEQL * HD, (long long)SEQL * HD, (long long)SEQL * SEQL);

    // 6) softmax rows
    softmax_k<<<HEADS * SEQL, 256>>>();

    // 7) attn = P @ V  -> concat buffer columns [0:HID), interleaved by head
    gemm_nt<<<dim3(HD / BN, SEQL / BM, HEADS), 256>>>(
        p_s, p_vt, nullptr, nullptr, nullptr, p_c,
        SEQL, SEQL, SEQL, C2K,
        (long long)SEQL * SEQL, (long long)HD * SEQL, (long long)HD);

    // 8) lin2 + gate + residual fused: out = x + gate * (c @ lin2_w^T + b)
    gemm_nt<<<dim3(HID / BN, SEQL / BM, 1), 256>>>(
        p_c, lin2_w, lin2_b, x, p_mod + 2 * HID, out,
        C2K, C2K, C2K, HID, 0, 0, 0);
}